// round 6
// baseline (speedup 1.0000x reference)
#include <cuda_runtime.h>
#include <math.h>

#define DEV_INLINE __device__ __forceinline__

// ---------------- problem constants ----------------
// B=8, N=1024, C=[256,512,1024], C2=512, KV=1792, H=4, EXPAND=4
// Restructured math (token-dim factored out of K/V projections):
//   X2 = LN(emb2)            [8192,512]
//   E  = LN(concat)          [8192,1792]
//   M[b]   = X2[b]^T E[b]                [512,1792]   (gemm TN, K=1024, split-K=2)
//   T1[b,h]= Wq[h]^T M[b]                [512,1792]   (gemm TN, K=512)
//   S[b,h] = T1[b,h] Wk[h] / sqrt(KV)    [512,1792]   (gemm NN, K=1792)
//   S <- softmax(instnorm(S)) rowwise over KV
//   G4[b,h]= Wv[h] S[b,h]^T              [1792,512]   (gemm NT, K=1792) -> reuses g_T1
//   G[b]   = sum_h G4[b,h]               (vector reduce)
//   ctx[b] = E[b] G[b] / H               [1024,512]   (gemm NN, K=1792)
//   cx2    = ctx Wout + emb2             (gemm NN + residual)
//   Xf     = LN(cx2); H1 = gelu(Xf fc1 + b1); out = H1 fc2 + b2 + cx2

// ---------------- scratch (static device memory; no allocs) ----------------
__device__ __align__(16) float  g_X2 [8192u*512u];
__device__ __align__(16) float  g_E  [8192u*1792u];
__device__ __align__(16) float  g_M  [8u*512u*1792u];
__device__ __align__(16) float  g_T1 [32u*512u*1792u];   // T1, then reused as G4
__device__ __align__(16) float  g_S  [32u*512u*1792u];   // split-K scratch, then scores
__device__ __align__(16) float  g_G  [8u*1792u*512u];
__device__ __align__(16) float  g_ctx[8192u*512u];
__device__ __align__(16) float  g_cx2[8192u*512u];
__device__ __align__(16) float  g_Xf [8192u*512u];
__device__ __align__(16) float  g_H1 [8192u*2048u];
__device__ __align__(16) double g_acc[64];

// ---------------- packed f32x2 helpers (sm_103a FFMA2 path) ----------------
DEV_INLINE void fma2(unsigned long long& c, unsigned long long a, unsigned long long b) {
    asm("fma.rn.f32x2 %0, %1, %2, %0;" : "+l"(c) : "l"(a), "l"(b));
}
DEV_INLINE float2 unpack2(unsigned long long v) {
    float2 r;
    asm("mov.b64 {%0, %1}, %2;" : "=f"(r.x), "=f"(r.y) : "l"(v));
    return r;
}

// ---------------- block reductions (blockDim == 256) ----------------
DEV_INLINE void blockReduce2(float& a, float& b) {
    __shared__ float sb[16];
    #pragma unroll
    for (int o = 16; o > 0; o >>= 1) {
        a += __shfl_down_sync(0xffffffffu, a, o);
        b += __shfl_down_sync(0xffffffffu, b, o);
    }
    int w = threadIdx.x >> 5, l = threadIdx.x & 31;
    if (l == 0) { sb[w] = a; sb[w + 8] = b; }
    __syncthreads();
    if (threadIdx.x < 32) {
        a = (l < 8) ? sb[l] : 0.f;
        b = (l < 8) ? sb[l + 8] : 0.f;
        #pragma unroll
        for (int o = 4; o > 0; o >>= 1) {
            a += __shfl_down_sync(0xffffffffu, a, o);
            b += __shfl_down_sync(0xffffffffu, b, o);
        }
        if (l == 0) { sb[0] = a; sb[1] = b; }
    }
    __syncthreads();
    a = sb[0]; b = sb[1];
    __syncthreads();
}

DEV_INLINE float blockReduceMax(float v) {
    __shared__ float sb[8];
    #pragma unroll
    for (int o = 16; o > 0; o >>= 1) v = fmaxf(v, __shfl_down_sync(0xffffffffu, v, o));
    int w = threadIdx.x >> 5, l = threadIdx.x & 31;
    if (l == 0) sb[w] = v;
    __syncthreads();
    if (threadIdx.x < 32) {
        v = (l < 8) ? sb[l] : -1e30f;
        #pragma unroll
        for (int o = 4; o > 0; o >>= 1) v = fmaxf(v, __shfl_down_sync(0xffffffffu, v, o));
        if (l == 0) sb[0] = v;
    }
    __syncthreads();
    v = sb[0];
    __syncthreads();
    return v;
}

DEV_INLINE float blockReduceSum(float v) {
    __shared__ float sb[8];
    #pragma unroll
    for (int o = 16; o > 0; o >>= 1) v += __shfl_down_sync(0xffffffffu, v, o);
    int w = threadIdx.x >> 5, l = threadIdx.x & 31;
    if (l == 0) sb[w] = v;
    __syncthreads();
    if (threadIdx.x < 32) {
        v = (l < 8) ? sb[l] : 0.f;
        #pragma unroll
        for (int o = 4; o > 0; o >>= 1) v += __shfl_down_sync(0xffffffffu, v, o);
        if (l == 0) sb[0] = v;
    }
    __syncthreads();
    v = sb[0];
    __syncthreads();
    return v;
}

// ---------------- generic SGEMM tile (128x128x16, 256 thr, 8x8/thr) ----------------
// A is stored DUPLICATED in smem: As2[k][2m] = As2[k][2m+1] = A[k][m], so the
// microkernel reads ready-made f32x2 pairs (no register-duplication MOVs).
// DIRECT=1: global tile is [16 x 128] (row = k). DIRECT=0: [128 x 16], transposed.
template<int DIRECT>
DEV_INLINE void ld_tile(const float* __restrict__ P, int ld, int t, int off0,
                        int rT, int cT, int rN, int cN, float4& v0, float4& v1) {
    if (DIRECT) {
        const float* p = P + (long)(t * 16 + rT) * ld + off0 + cT * 4;
        v0 = *(const float4*)p;
        v1 = *(const float4*)(p + 8 * (long)ld);
    } else {
        const float* p = P + (long)(off0 + rN) * ld + t * 16 + cN * 4;
        v0 = *(const float4*)p;
        v1 = *(const float4*)(p + 64 * (long)ld);
    }
}

// A-side store with duplication into As2[16][256].
template<int DIRECT>
DEV_INLINE void st_tileA(float Sm[16][256], int rT, int cT, int rN, int cN,
                         float4 v0, float4 v1) {
    if (DIRECT) {
        *(float4*)&Sm[rT][cT * 8]         = make_float4(v0.x, v0.x, v0.y, v0.y);
        *(float4*)&Sm[rT][cT * 8 + 4]     = make_float4(v0.z, v0.z, v0.w, v0.w);
        *(float4*)&Sm[rT + 8][cT * 8]     = make_float4(v1.x, v1.x, v1.y, v1.y);
        *(float4*)&Sm[rT + 8][cT * 8 + 4] = make_float4(v1.z, v1.z, v1.w, v1.w);
    } else {
        float va[4] = {v0.x, v0.y, v0.z, v0.w};
        float vb[4] = {v1.x, v1.y, v1.z, v1.w};
        #pragma unroll
        for (int j = 0; j < 4; j++) {
            *(float2*)&Sm[cN * 4 + j][2 * rN]         = make_float2(va[j], va[j]);
            *(float2*)&Sm[cN * 4 + j][2 * rN + 128]   = make_float2(vb[j], vb[j]);
        }
    }
}

// B-side store (no duplication), Bs[16][128].
template<int DIRECT>
DEV_INLINE void st_tileB(float Sm[16][128], int rT, int cT, int rN, int cN,
                         float4 v0, float4 v1) {
    if (DIRECT) {
        *(float4*)&Sm[rT][cT * 4]     = v0;
        *(float4*)&Sm[rT + 8][cT * 4] = v1;
    } else {
        Sm[cN * 4 + 0][rN] = v0.x; Sm[cN * 4 + 1][rN] = v0.y;
        Sm[cN * 4 + 2][rN] = v0.z; Sm[cN * 4 + 3][rN] = v0.w;
        Sm[cN * 4 + 0][rN + 64] = v1.x; Sm[cN * 4 + 1][rN + 64] = v1.y;
        Sm[cN * 4 + 2][rN + 64] = v1.z; Sm[cN * 4 + 3][rN + 64] = v1.w;
    }
}

// Packed microtile: 8 rows x 4 column-pairs of f32x2 accumulators.
// Per k-step: 4 LDS.128 (A pairs) + 2 LDS.128 (B pairs) + 32 FFMA2. No MOVs.
DEV_INLINE void mma_tile(const float As2[16][256], const float Bs[16][128],
                         int ty, int tx, unsigned long long acc2[8][4]) {
    #pragma unroll
    for (int k = 0; k < 16; k++) {
        const ulonglong2* ap = (const ulonglong2*)&As2[k][ty * 16];   // 64B aligned
        ulonglong2 p0 = ap[0], p1 = ap[1], p2 = ap[2], p3 = ap[3];
        const ulonglong2* bp = (const ulonglong2*)&Bs[k][tx * 8];     // 32B aligned
        ulonglong2 q0 = bp[0], q1 = bp[1];
        unsigned long long ad[8] = {p0.x, p0.y, p1.x, p1.y, p2.x, p2.y, p3.x, p3.y};
        unsigned long long b0 = q0.x, b1 = q0.y, b2 = q1.x, b3 = q1.y;
        #pragma unroll
        for (int i = 0; i < 8; i++) {
            fma2(acc2[i][0], ad[i], b0);
            fma2(acc2[i][1], ad[i], b1);
            fma2(acc2[i][2], ad[i], b2);
            fma2(acc2[i][3], ad[i], b3);
        }
    }
}

// TRA=1: A stored [K,M]; TRA=0: A stored [M,K]. TRB=0: B stored [K,N]; TRB=1: [N,K].
// z-batched: operand offset = (z/div)*sDiv + (z%div)*sMod. Optional inner h-sum
// (flattened into the k-tile stream). EPI: 0 none, 1 +add, 2 bias+gelu, 3 bias+add.
// Double-buffered smem: ONE __syncthreads per k-tile; smem store of tile t+1
// happens after the mma on tile t so LDG latency hides behind FFMA2 work.
template<int TRA, int TRB, int EPI>
__global__ __launch_bounds__(256, 2)
void gemm_k(const float* __restrict__ Ag, const float* __restrict__ Bg,
            float* __restrict__ Cg,
            int K, int lda, int ldb, int ldc, float alpha,
            int aDiv, long aSDiv, long aSMod,
            int bDiv, long bSDiv, long bSMod, long cStr,
            int numH, long aHS, long bHS,
            const float* __restrict__ bias, const float* __restrict__ addp)
{
    __shared__ float As[2][16][256];   // duplicated A: 32 KB
    __shared__ float Bs[2][16][128];   // 16 KB  (total 48 KB static)
    const int z = blockIdx.z;
    const float* A = Ag + (long)(z / aDiv) * aSDiv + (long)(z % aDiv) * aSMod;
    const float* Bp = Bg + (long)(z / bDiv) * bSDiv + (long)(z % bDiv) * bSMod;
    float* C0 = Cg + (long)z * cStr;
    const int m0 = blockIdx.y * 128, n0 = blockIdx.x * 128;
    const int tid = threadIdx.x;
    const int ty = tid >> 4, tx = tid & 15;
    const int rT = tid >> 5, cT = tid & 31;
    const int rN = tid >> 2, cN = tid & 3;

    unsigned long long acc2[8][4];
    #pragma unroll
    for (int i = 0; i < 8; i++)
        #pragma unroll
        for (int j = 0; j < 4; j++) acc2[i][j] = 0ull;

    const int nt = K / 16;
    const int ntTot = numH * nt;
    float4 av0, av1, bv0, bv1;

    // prologue: tile 0 into buffer 0
    ld_tile<TRA>(A, lda, 0, m0, rT, cT, rN, cN, av0, av1);
    ld_tile<TRB ? 0 : 1>(Bp, ldb, 0, n0, rT, cT, rN, cN, bv0, bv1);
    st_tileA<TRA>(As[0], rT, cT, rN, cN, av0, av1);
    st_tileB<TRB ? 0 : 1>(Bs[0], rT, cT, rN, cN, bv0, bv1);
    __syncthreads();

    int buf = 0;
    int kk = 0;
    for (int tt = 1; tt < ntTot; ++tt) {
        ++kk;
        if (kk == nt) { kk = 0; A += aHS; Bp += bHS; }
        ld_tile<TRA>(A, lda, kk, m0, rT, cT, rN, cN, av0, av1);          // prefetch (LDG)
        ld_tile<TRB ? 0 : 1>(Bp, ldb, kk, n0, rT, cT, rN, cN, bv0, bv1);
        mma_tile(As[buf], Bs[buf], ty, tx, acc2);                        // hide LDG here
        st_tileA<TRA>(As[buf ^ 1], rT, cT, rN, cN, av0, av1);
        st_tileB<TRB ? 0 : 1>(Bs[buf ^ 1], rT, cT, rN, cN, bv0, bv1);
        __syncthreads();
        buf ^= 1;
    }
    mma_tile(As[buf], Bs[buf], ty, tx, acc2);

    // vectorized epilogue: 8 consecutive cols per thread -> 2x float4
    const int col0 = n0 + tx * 8;
    #pragma unroll
    for (int i = 0; i < 8; i++) {
        const int row = m0 + ty * 8 + i;
        float vv[8];
        #pragma unroll
        for (int jp = 0; jp < 4; jp++) {
            float2 pv = unpack2(acc2[i][jp]);
            vv[jp * 2] = pv.x * alpha;
            vv[jp * 2 + 1] = pv.y * alpha;
        }
        if (EPI == 2 || EPI == 3) {
            float4 bb0 = *(const float4*)&bias[col0];
            float4 bb1 = *(const float4*)&bias[col0 + 4];
            vv[0] += bb0.x; vv[1] += bb0.y; vv[2] += bb0.z; vv[3] += bb0.w;
            vv[4] += bb1.x; vv[5] += bb1.y; vv[6] += bb1.z; vv[7] += bb1.w;
        }
        if (EPI == 1 || EPI == 3) {
            float4 r0 = *(const float4*)&addp[(long)row * ldc + col0];
            float4 r1 = *(const float4*)&addp[(long)row * ldc + col0 + 4];
            vv[0] += r0.x; vv[1] += r0.y; vv[2] += r0.z; vv[3] += r0.w;
            vv[4] += r1.x; vv[5] += r1.y; vv[6] += r1.z; vv[7] += r1.w;
        }
        if (EPI == 2) {
            #pragma unroll
            for (int u = 0; u < 8; u++)
                vv[u] = 0.5f * vv[u] * (1.0f + erff(vv[u] * 0.70710678118654752f));
        }
        float4 o0 = make_float4(vv[0], vv[1], vv[2], vv[3]);
        float4 o1 = make_float4(vv[4], vv[5], vv[6], vv[7]);
        *(float4*)&C0[(long)row * ldc + col0]     = o0;
        *(float4*)&C0[(long)row * ldc + col0 + 4] = o1;
    }
}

// ---------------- fused input layernorms ----------------
__global__ void ln_fused_k(const float* __restrict__ e1, const float* __restrict__ e2,
                           const float* __restrict__ e3,
                           const float* __restrict__ g1, const float* __restrict__ b1,
                           const float* __restrict__ ga, const float* __restrict__ ba,
                           float* __restrict__ X2, float* __restrict__ E)
{
    const long r = blockIdx.x;
    const int t = threadIdx.x;
    const float* p1 = e1 + r * 256;
    const float* p2 = e2 + r * 512;
    const float* p3 = e3 + r * 1024;
    float v1  = p1[t];
    float v2a = p2[t], v2b = p2[t + 256];
    float w0 = p3[t], w1 = p3[t + 256], w2 = p3[t + 512], w3 = p3[t + 768];

    float s2 = v2a + v2b;
    float q2 = v2a * v2a + v2b * v2b;
    float sa = s2 + v1 + w0 + w1 + w2 + w3;
    float qa = q2 + v1 * v1 + w0 * w0 + w1 * w1 + w2 * w2 + w3 * w3;
    blockReduce2(s2, q2);
    blockReduce2(sa, qa);

    float m2  = s2 * (1.f / 512.f);
    float rs2 = rsqrtf(q2 * (1.f / 512.f) - m2 * m2 + 1e-6f);
    float mA  = sa * (1.f / 1792.f);
    float rsA = rsqrtf(qa * (1.f / 1792.f) - mA * mA + 1e-6f);

    float* x2r = X2 + r * 512;
    x2r[t]       = (v2a - m2) * rs2 * g1[t]       + b1[t];
    x2r[t + 256] = (v2b - m2) * rs2 * g1[t + 256] + b1[t + 256];

    float* Er = E + r * 1792;
    Er[t]        = (v1  - mA) * rsA * ga[t]        + ba[t];
    Er[256 + t]  = (v2a - mA) * rsA * ga[256 + t]  + ba[256 + t];
    Er[512 + t]  = (v2b - mA) * rsA * ga[512 + t]  + ba[512 + t];
    Er[768 + t]  = (w0  - mA) * rsA * ga[768 + t]  + ba[768 + t];
    Er[1024 + t] = (w1  - mA) * rsA * ga[1024 + t] + ba[1024 + t];
    Er[1280 + t] = (w2  - mA) * rsA * ga[1280 + t] + ba[1280 + t];
    Er[1536 + t] = (w3  - mA) * rsA * ga[1536 + t] + ba[1536 + t];
}

// ---------------- row LN (width 512) ----------------
__global__ void ln_row512_k(const float* __restrict__ X, const float* __restrict__ g,
                            const float* __restrict__ b, float* __restrict__ Y)
{
    const long r = blockIdx.x;
    const int t = threadIdx.x;
    const float* p = X + r * 512;
    float v0 = p[t], v1 = p[t + 256];
    float s = v0 + v1, q = v0 * v0 + v1 * v1;
    blockReduce2(s, q);
    float m  = s * (1.f / 512.f);
    float rs = rsqrtf(q * (1.f / 512.f) - m * m + 1e-6f);
    Y[r * 512 + t]       = (v0 - m) * rs * g[t]       + b[t];
    Y[r * 512 + t + 256] = (v1 - m) * rs * g[t + 256] + b[t + 256];
}

// ---------------- instance-norm stats + softmax ----------------
__global__ void zero_acc_k(double* __restrict__ acc) {
    if (threadIdx.x < 64) acc[threadIdx.x] = 0.0;
}

__global__ void in_stats_k(const float* __restrict__ S, double* __restrict__ acc) {
    const int z = blockIdx.x;      // 32 maps
    const int ch = blockIdx.y;     // 16 chunks per map
    const float4* p = (const float4*)(S + (long)z * 917504 + (long)ch * 57344);
    float s = 0.f, q = 0.f;
    for (int i = threadIdx.x; i < 14336; i += 256) {
        float4 v = p[i];
        s += v.x + v.y + v.z + v.w;
        q = fmaf(v.x, v.x, q); q = fmaf(v.y, v.y, q);
        q = fmaf(v.z, v.z, q); q = fmaf(v.w, v.w, q);
    }
    blockReduce2(s, q);
    if (threadIdx.x == 0) {
        atomicAdd(&acc[z * 2], (double)s);
        atomicAdd(&acc[z * 2 + 1], (double)q);
    }
}

__global__ void inorm_softmax_k(float* __restrict__ S, const double* __restrict__ acc) {
    const int z = blockIdx.y;   // map (b*H+h)
    const int c = blockIdx.x;   // row within map
    const int t = threadIdx.x;
    const double cnt = 917504.0;
    double mu = acc[z * 2] / cnt;
    double va = acc[z * 2 + 1] / cnt - mu * mu;
    float mean = (float)mu;
    float rstd = rsqrtf((float)va + 1e-5f);

    float* row = S + (long)z * 917504 + (long)c * 1792;
    float x[7];
    float mx = -1e30f;
    #pragma unroll
    for (int i = 0; i < 7; i++) {
        x[i] = (row[t + i * 256] - mean) * rstd;
        mx = fmaxf(mx, x[i]);
    }
    mx = blockReduceMax(mx);
    float s = 0.f;
    #pragma unroll
    for (int i = 0; i < 7; i++) { x[i] = expf(x[i] - mx); s += x[i]; }
    s = blockReduceSum(s);
    float inv = 1.f / s;
    #pragma unroll
    for (int i = 0; i < 7; i++) row[t + i * 256] = x[i] * inv;
}

// ---------------- 4-way head reduce: G[b] = sum_h G4[b*4+h] ----------------
__global__ void reduce_g_k(const float4* __restrict__ G4, float4* __restrict__ G) {
    const long j = (long)blockIdx.x * 256 + threadIdx.x;   // 8 * 229376 total
    const long S4 = 917504 / 4;                            // 229376 float4 per map
    const long b = j / S4, off = j - b * S4;
    const float4* p = G4 + b * 4 * S4 + off;
    float4 r = p[0];
    float4 a1 = p[S4], a2 = p[2 * S4], a3 = p[3 * S4];
    r.x += a1.x + a2.x + a3.x;
    r.y += a1.y + a2.y + a3.y;
    r.z += a1.z + a2.z + a3.z;
    r.w += a1.w + a2.w + a3.w;
    G[j] = r;
}

// ---------------- split-K pair reduce: M[b] = P[2b] + P[2b+1] ----------------
__global__ void reduce_m_k(const float4* __restrict__ P, float4* __restrict__ M) {
    const long j = (long)blockIdx.x * 256 + threadIdx.x;   // 8 * 229376 total
    const long S4 = 917504 / 4;                            // 229376 float4 per map
    const long b = j / S4, off = j - b * S4;
    const float4* p = P + b * 2 * S4 + off;
    float4 r = p[0];
    float4 a1 = p[S4];
    r.x += a1.x; r.y += a1.y; r.z += a1.z; r.w += a1.w;
    M[j] = r;
}

// ---------------- launcher ----------------
extern "C" void kernel_launch(void* const* d_in, const int* in_sizes, int n_in,
                              void* d_out, int out_size)
{
    const float* emb1    = (const float*)d_in[0];
    const float* emb2    = (const float*)d_in[1];
    const float* emb3    = (const float*)d_in[2];
    const float* Wq      = (const float*)d_in[3];
    const float* Wk      = (const float*)d_in[4];
    const float* Wv      = (const float*)d_in[5];
    const float* Wout    = (const float*)d_in[6];
    const float* ln1_g   = (const float*)d_in[7];
    const float* ln1_b   = (const float*)d_in[8];
    const float* lnall_g = (const float*)d_in[9];
    const float* lnall_b = (const float*)d_in[10];
    const float* lnffn_g = (const float*)d_in[11];
    const float* lnffn_b = (const float*)d_in[12];
    const float* fc1_w   = (const float*)d_in[13];
    const float* fc1_b   = (const float*)d_in[14];
    const float* fc2_w   = (const float*)d_in[15];
    const float* fc2_b   = (const float*)d_in[16];

    float *X2, *E, *Mb, *T1, *S, *G, *CTX, *CX2, *XF, *H1;
    double* ACC;
    cudaGetSymbolAddress((void**)&X2,  g_X2);
    cudaGetSymbolAddress((void**)&E,   g_E);
    cudaGetSymbolAddress((void**)&Mb,  g_M);
    cudaGetSymbolAddress((void**)&T1,  g_T1);
    cudaGetSymbolAddress((void**)&S,   g_S);
    cudaGetSymbolAddress((void**)&G,   g_G);
    cudaGetSymbolAddress((void**)&CTX, g_ctx);
    cudaGetSymbolAddress((void**)&CX2, g_cx2);
    cudaGetSymbolAddress((void**)&XF,  g_Xf);
    cudaGetSymbolAddress((void**)&H1,  g_H1);
    cudaGetSymbolAddress((void**)&ACC, g_acc);

    const long SZmap = 512L * 1792L;          // 917504
    const float inv_sqrt_kv = 1.0f / sqrtf(1792.0f);

    // 1) LNs
    ln_fused_k<<<8192, 256>>>(emb1, emb2, emb3, ln1_g, ln1_b, lnall_g, lnall_b, X2, E);

    // 2) split-K=2: Mpart[b,k2] = X2[b, k2*512:(k2+1)*512]^T E[b, same rows]
    //    z = b*2 + k2, 896 CTAs (3.03 waves). Partials land in g_S (dead here).
    gemm_k<1, 0, 0><<<dim3(14, 4, 16), 256>>>(X2, E, S,
        512, 512, 1792, 1792, 1.0f,
        2, 1024L * 512, 512L * 512, 2, 1024L * 1792, 512L * 1792, SZmap,
        1, 0, 0, nullptr, nullptr);

    // 2b) M[b] = Mpart[b,0] + Mpart[b,1]
    reduce_m_k<<<7168, 256>>>((const float4*)S, (float4*)Mb);

    // 3) T1[b,h] = Wq[h]^T M[b]   (TN, K=512) grid z = b*H+h
    gemm_k<1, 0, 0><<<dim3(14, 4, 32), 256>>>(Wq, Mb, T1,
        512, 512, 1792, 1792, 1.0f,
        4, 0, 512L * 512, 4, SZmap, 0, SZmap,
        1, 0, 0, nullptr, nullptr);

    // 4) S[b,h] = T1[b,h] Wk[h] / sqrt(KV)   (NN, K=1792)
    gemm_k<0, 0, 0><<<dim3(14, 4, 32), 256>>>(T1, Wk, S,
        1792, 1792, 1792, 1792, inv_sqrt_kv,
        1, SZmap, 0, 4, 0, 1792L * 1792, SZmap,
        1, 0, 0, nullptr, nullptr);

    // 5) instance-norm stats + softmax (in place on S)
    zero_acc_k<<<1, 64>>>(ACC);
    in_stats_k<<<dim3(32, 16), 256>>>(S, ACC);
    inorm_softmax_k<<<dim3(512, 32), 256>>>(S, ACC);

    // 6) G4[b,h] = Wv[h] @ S[b,h]^T   (NT, K=1792) z = b*4+h, 1792 CTAs (6 waves)
    //    T1 is dead after step 4 -> reuse as G4 scratch.
    gemm_k<0, 1, 0><<<dim3(4, 14, 32), 256>>>(Wv, S, T1,
        1792, 1792, 1792, 512, 1.0f,
        4, 0, 1792L * 1792, 1, SZmap, 0, SZmap,
        1, 0, 0, nullptr, nullptr);

    // 6b) G[b] = sum_h G4[b,h]
    reduce_g_k<<<7168, 256>>>((const float4*)T1, (float4*)G);

    // 7) ctx[b] = E[b] G[b] / H   (NN, K=1792) grid(4, 8, 8)
    gemm_k<0, 0, 0><<<dim3(4, 8, 8), 256>>>(E, G, CTX,
        1792, 1792, 512, 512, 0.25f,
        1, 1024L * 1792, 0, 1, 1792L * 512, 0, 1024L * 512,
        1, 0, 0, nullptr, nullptr);

    // 8) cx2 = ctx Wout + emb2   (NN, K=512, EPI=add)
    gemm_k<0, 0, 1><<<dim3(4, 64, 1), 256>>>(CTX, Wout, CX2,
        512, 512, 512, 512, 1.0f,
        1, 0, 0, 1, 0, 0, 0,
        1, 0, 0, nullptr, emb2);

    // 9) Xf = LN(cx2)
    ln_row512_k<<<8192, 256>>>(CX2, lnffn_g, lnffn_b, XF);

    // 10) H1 = gelu(Xf fc1 + b1)   (NN, K=512, EPI=bias+gelu)
    gemm_k<0, 0, 2><<<dim3(16, 64, 1), 256>>>(XF, fc1_w, H1,
        512, 512, 2048, 2048, 1.0f,
        1, 0, 0, 1, 0, 0, 0,
        1, 0, 0, fc1_b, nullptr);

    // 11) out = H1 fc2 + b2 + cx2   (NN, K=2048, EPI=bias+add)
    gemm_k<0, 0, 3><<<dim3(4, 64, 1), 256>>>(H1, fc2_w, (float*)d_out,
        2048, 2048, 512, 512, 1.0f,
        1, 0, 0, 1, 0, 0, 0,
        1, 0, 0, fc2_b, CX2);
}

// round 8
// speedup vs baseline: 1.2658x; 1.2658x over previous
#include <cuda_runtime.h>
#include <math.h>

#define DEV_INLINE __device__ __forceinline__

// ---------------- problem constants ----------------
// B=8, N=1024, C=[256,512,1024], C2=512, KV=1792, H=4, EXPAND=4
// Restructured math (token-dim factored out of K/V projections):
//   X2 = LN(emb2)            [8192,512]
//   E  = LN(concat)          [8192,1792]
//   M[b]   = X2[b]^T E[b]                [512,1792]   (gemm TN, K=1024, split-K=2)
//   T1[b,h]= Wq[h]^T M[b]                [512,1792]   (gemm TN, K=512)
//   S[b,h] = T1[b,h] Wk[h] / sqrt(KV)    [512,1792]   (gemm NN, K=1792)
//   S <- softmax(instnorm(S)) rowwise over KV
//   G4[b,h]= Wv[h] S[b,h]^T              [1792,512]   (gemm NT, K=1792) -> reuses g_T1
//   G[b]   = sum_h G4[b,h]               (vector reduce)
//   ctx[b] = E[b] G[b] / H               [1024,512]   (gemm NN, K=1792)
//   cx2    = ctx Wout + emb2             (gemm NN + residual)
//   Xf     = LN(cx2); H1 = gelu(Xf fc1 + b1); out = H1 fc2 + b2 + cx2

// ---------------- scratch (static device memory; no allocs) ----------------
__device__ __align__(16) float  g_X2 [8192u*512u];
__device__ __align__(16) float  g_E  [8192u*1792u];
__device__ __align__(16) float  g_M  [8u*512u*1792u];
__device__ __align__(16) float  g_T1 [32u*512u*1792u];   // T1, then reused as G4
__device__ __align__(16) float  g_S  [32u*512u*1792u];   // split-K scratch, then scores
__device__ __align__(16) float  g_G  [8u*1792u*512u];
__device__ __align__(16) float  g_ctx[8192u*512u];
__device__ __align__(16) float  g_cx2[8192u*512u];
__device__ __align__(16) float  g_Xf [8192u*512u];
__device__ __align__(16) float  g_H1 [8192u*2048u];
__device__ __align__(16) double g_acc[64];

// ---------------- packed f32x2 helpers (sm_103a FFMA2 path) ----------------
DEV_INLINE unsigned long long dup2(float a) {
    unsigned long long r;
    asm("mov.b64 %0, {%1, %1};" : "=l"(r) : "f"(a));
    return r;
}
DEV_INLINE void fma2(unsigned long long& c, unsigned long long a, unsigned long long b) {
    asm("fma.rn.f32x2 %0, %1, %2, %0;" : "+l"(c) : "l"(a), "l"(b));
}
DEV_INLINE float2 unpack2(unsigned long long v) {
    float2 r;
    asm("mov.b64 {%0, %1}, %2;" : "=f"(r.x), "=f"(r.y) : "l"(v));
    return r;
}

// ---------------- block reductions (blockDim == 256) ----------------
DEV_INLINE void blockReduce2(float& a, float& b) {
    __shared__ float sb[16];
    #pragma unroll
    for (int o = 16; o > 0; o >>= 1) {
        a += __shfl_down_sync(0xffffffffu, a, o);
        b += __shfl_down_sync(0xffffffffu, b, o);
    }
    int w = threadIdx.x >> 5, l = threadIdx.x & 31;
    if (l == 0) { sb[w] = a; sb[w + 8] = b; }
    __syncthreads();
    if (threadIdx.x < 32) {
        a = (l < 8) ? sb[l] : 0.f;
        b = (l < 8) ? sb[l + 8] : 0.f;
        #pragma unroll
        for (int o = 4; o > 0; o >>= 1) {
            a += __shfl_down_sync(0xffffffffu, a, o);
            b += __shfl_down_sync(0xffffffffu, b, o);
        }
        if (l == 0) { sb[0] = a; sb[1] = b; }
    }
    __syncthreads();
    a = sb[0]; b = sb[1];
    __syncthreads();
}

DEV_INLINE float blockReduceMax(float v) {
    __shared__ float sb[8];
    #pragma unroll
    for (int o = 16; o > 0; o >>= 1) v = fmaxf(v, __shfl_down_sync(0xffffffffu, v, o));
    int w = threadIdx.x >> 5, l = threadIdx.x & 31;
    if (l == 0) sb[w] = v;
    __syncthreads();
    if (threadIdx.x < 32) {
        v = (l < 8) ? sb[l] : -1e30f;
        #pragma unroll
        for (int o = 4; o > 0; o >>= 1) v = fmaxf(v, __shfl_down_sync(0xffffffffu, v, o));
        if (l == 0) sb[0] = v;
    }
    __syncthreads();
    v = sb[0];
    __syncthreads();
    return v;
}

DEV_INLINE float blockReduceSum(float v) {
    __shared__ float sb[8];
    #pragma unroll
    for (int o = 16; o > 0; o >>= 1) v += __shfl_down_sync(0xffffffffu, v, o);
    int w = threadIdx.x >> 5, l = threadIdx.x & 31;
    if (l == 0) sb[w] = v;
    __syncthreads();
    if (threadIdx.x < 32) {
        v = (l < 8) ? sb[l] : 0.f;
        #pragma unroll
        for (int o = 4; o > 0; o >>= 1) v += __shfl_down_sync(0xffffffffu, v, o);
        if (l == 0) sb[0] = v;
    }
    __syncthreads();
    v = sb[0];
    __syncthreads();
    return v;
}

// ---------------- generic SGEMM tile (128x128x16, 256 thr, 8x8/thr) ----------------
// DIRECT=1: global tile is [16 x 128] (row = k), stores straight into smem [k][x].
// DIRECT=0: global tile is [128 x 16] (row = x), loads along k and transposes.
template<int DIRECT>
DEV_INLINE void ld_tile(const float* __restrict__ P, int ld, int t, int off0,
                        int rT, int cT, int rN, int cN, float4& v0, float4& v1) {
    if (DIRECT) {
        const float* p = P + (long)(t * 16 + rT) * ld + off0 + cT * 4;
        v0 = *(const float4*)p;
        v1 = *(const float4*)(p + 8 * (long)ld);
    } else {
        const float* p = P + (long)(off0 + rN) * ld + t * 16 + cN * 4;
        v0 = *(const float4*)p;
        v1 = *(const float4*)(p + 64 * (long)ld);
    }
}

// smem store (no duplication), Sm[16][128].
template<int DIRECT>
DEV_INLINE void st_tile(float Sm[16][128], int rT, int cT, int rN, int cN,
                        float4 v0, float4 v1) {
    if (DIRECT) {
        *(float4*)&Sm[rT][cT * 4]     = v0;
        *(float4*)&Sm[rT + 8][cT * 4] = v1;
    } else {
        Sm[cN * 4 + 0][rN] = v0.x; Sm[cN * 4 + 1][rN] = v0.y;
        Sm[cN * 4 + 2][rN] = v0.z; Sm[cN * 4 + 3][rN] = v0.w;
        Sm[cN * 4 + 0][rN + 64] = v1.x; Sm[cN * 4 + 1][rN + 64] = v1.y;
        Sm[cN * 4 + 2][rN + 64] = v1.z; Sm[cN * 4 + 3][rN + 64] = v1.w;
    }
}

// Packed microtile: 8 rows x 4 column-pairs of f32x2 accumulators.
// Per k-step: 2 LDS.128 (A) + 2 LDS.128 (B pairs) + 8 MOV64 dup + 32 FFMA2.
// LSU wavefronts halved vs duplicated-A layout (the measured 93% L1 bottleneck);
// MOVs ride the alu pipe in parallel with fma.
DEV_INLINE void mma_tile(const float As[16][128], const float Bs[16][128],
                         int ty, int tx, unsigned long long acc2[8][4]) {
    #pragma unroll
    for (int k = 0; k < 16; k++) {
        float4 a0 = *(const float4*)&As[k][ty * 8];
        float4 a1 = *(const float4*)&As[k][ty * 8 + 4];
        const ulonglong2* bp = (const ulonglong2*)&Bs[k][tx * 8];     // 32B aligned
        ulonglong2 q0 = bp[0], q1 = bp[1];
        unsigned long long b0 = q0.x, b1 = q0.y, b2 = q1.x, b3 = q1.y;
        float ar[8] = {a0.x, a0.y, a0.z, a0.w, a1.x, a1.y, a1.z, a1.w};
        #pragma unroll
        for (int i = 0; i < 8; i++) {
            unsigned long long ad = dup2(ar[i]);
            fma2(acc2[i][0], ad, b0);
            fma2(acc2[i][1], ad, b1);
            fma2(acc2[i][2], ad, b2);
            fma2(acc2[i][3], ad, b3);
        }
    }
}

// TRA=1: A stored [K,M]; TRA=0: A stored [M,K]. TRB=0: B stored [K,N]; TRB=1: [N,K].
// z-batched: operand offset = (z/div)*sDiv + (z%div)*sMod. Optional inner h-sum
// (flattened into the k-tile stream). EPI: 0 none, 1 +add, 2 bias+gelu, 3 bias+add.
// Double-buffered smem: ONE __syncthreads per k-tile; smem store of tile t+1
// happens after the mma on tile t so LDG latency hides behind FFMA2 work.
template<int TRA, int TRB, int EPI>
__global__ __launch_bounds__(256, 2)
void gemm_k(const float* __restrict__ Ag, const float* __restrict__ Bg,
            float* __restrict__ Cg,
            int K, int lda, int ldb, int ldc, float alpha,
            int aDiv, long aSDiv, long aSMod,
            int bDiv, long bSDiv, long bSMod, long cStr,
            int numH, long aHS, long bHS,
            const float* __restrict__ bias, const float* __restrict__ addp)
{
    __shared__ float As[2][16][128];   // 16 KB
    __shared__ float Bs[2][16][128];   // 16 KB  (total 32 KB)
    const int z = blockIdx.z;
    const float* A = Ag + (long)(z / aDiv) * aSDiv + (long)(z % aDiv) * aSMod;
    const float* Bp = Bg + (long)(z / bDiv) * bSDiv + (long)(z % bDiv) * bSMod;
    float* C0 = Cg + (long)z * cStr;
    const int m0 = blockIdx.y * 128, n0 = blockIdx.x * 128;
    const int tid = threadIdx.x;
    const int ty = tid >> 4, tx = tid & 15;
    const int rT = tid >> 5, cT = tid & 31;
    const int rN = tid >> 2, cN = tid & 3;

    unsigned long long acc2[8][4];
    #pragma unroll
    for (int i = 0; i < 8; i++)
        #pragma unroll
        for (int j = 0; j < 4; j++) acc2[i][j] = 0ull;

    const int nt = K / 16;
    const int ntTot = numH * nt;
    float4 av0, av1, bv0, bv1;

    // prologue: tile 0 into buffer 0
    ld_tile<TRA>(A, lda, 0, m0, rT, cT, rN, cN, av0, av1);
    ld_tile<TRB ? 0 : 1>(Bp, ldb, 0, n0, rT, cT, rN, cN, bv0, bv1);
    st_tile<TRA>(As[0], rT, cT, rN, cN, av0, av1);
    st_tile<TRB ? 0 : 1>(Bs[0], rT, cT, rN, cN, bv0, bv1);
    __syncthreads();

    int buf = 0;
    int kk = 0;
    for (int tt = 1; tt < ntTot; ++tt) {
        ++kk;
        if (kk == nt) { kk = 0; A += aHS; Bp += bHS; }
        ld_tile<TRA>(A, lda, kk, m0, rT, cT, rN, cN, av0, av1);          // prefetch (LDG)
        ld_tile<TRB ? 0 : 1>(Bp, ldb, kk, n0, rT, cT, rN, cN, bv0, bv1);
        mma_tile(As[buf], Bs[buf], ty, tx, acc2);                        // hide LDG here
        st_tile<TRA>(As[buf ^ 1], rT, cT, rN, cN, av0, av1);
        st_tile<TRB ? 0 : 1>(Bs[buf ^ 1], rT, cT, rN, cN, bv0, bv1);
        __syncthreads();
        buf ^= 1;
    }
    mma_tile(As[buf], Bs[buf], ty, tx, acc2);

    // vectorized epilogue: 8 consecutive cols per thread -> 2x float4
    const int col0 = n0 + tx * 8;
    #pragma unroll
    for (int i = 0; i < 8; i++) {
        const int row = m0 + ty * 8 + i;
        float vv[8];
        #pragma unroll
        for (int jp = 0; jp < 4; jp++) {
            float2 pv = unpack2(acc2[i][jp]);
            vv[jp * 2] = pv.x * alpha;
            vv[jp * 2 + 1] = pv.y * alpha;
        }
        if (EPI == 2 || EPI == 3) {
            float4 bb0 = *(const float4*)&bias[col0];
            float4 bb1 = *(const float4*)&bias[col0 + 4];
            vv[0] += bb0.x; vv[1] += bb0.y; vv[2] += bb0.z; vv[3] += bb0.w;
            vv[4] += bb1.x; vv[5] += bb1.y; vv[6] += bb1.z; vv[7] += bb1.w;
        }
        if (EPI == 1 || EPI == 3) {
            float4 r0 = *(const float4*)&addp[(long)row * ldc + col0];
            float4 r1 = *(const float4*)&addp[(long)row * ldc + col0 + 4];
            vv[0] += r0.x; vv[1] += r0.y; vv[2] += r0.z; vv[3] += r0.w;
            vv[4] += r1.x; vv[5] += r1.y; vv[6] += r1.z; vv[7] += r1.w;
        }
        if (EPI == 2) {
            #pragma unroll
            for (int u = 0; u < 8; u++)
                vv[u] = 0.5f * vv[u] * (1.0f + erff(vv[u] * 0.70710678118654752f));
        }
        float4 o0 = make_float4(vv[0], vv[1], vv[2], vv[3]);
        float4 o1 = make_float4(vv[4], vv[5], vv[6], vv[7]);
        *(float4*)&C0[(long)row * ldc + col0]     = o0;
        *(float4*)&C0[(long)row * ldc + col0 + 4] = o1;
    }
}

// ---------------- fused input layernorms ----------------
__global__ void ln_fused_k(const float* __restrict__ e1, const float* __restrict__ e2,
                           const float* __restrict__ e3,
                           const float* __restrict__ g1, const float* __restrict__ b1,
                           const float* __restrict__ ga, const float* __restrict__ ba,
                           float* __restrict__ X2, float* __restrict__ E)
{
    const long r = blockIdx.x;
    const int t = threadIdx.x;
    const float* p1 = e1 + r * 256;
    const float* p2 = e2 + r * 512;
    const float* p3 = e3 + r * 1024;
    float v1  = p1[t];
    float v2a = p2[t], v2b = p2[t + 256];
    float w0 = p3[t], w1 = p3[t + 256], w2 = p3[t + 512], w3 = p3[t + 768];

    float s2 = v2a + v2b;
    float q2 = v2a * v2a + v2b * v2b;
    float sa = s2 + v1 + w0 + w1 + w2 + w3;
    float qa = q2 + v1 * v1 + w0 * w0 + w1 * w1 + w2 * w2 + w3 * w3;
    blockReduce2(s2, q2);
    blockReduce2(sa, qa);

    float m2  = s2 * (1.f / 512.f);
    float rs2 = rsqrtf(q2 * (1.f / 512.f) - m2 * m2 + 1e-6f);
    float mA  = sa * (1.f / 1792.f);
    float rsA = rsqrtf(qa * (1.f / 1792.f) - mA * mA + 1e-6f);

    float* x2r = X2 + r * 512;
    x2r[t]       = (v2a - m2) * rs2 * g1[t]       + b1[t];
    x2r[t + 256] = (v2b - m2) * rs2 * g1[t + 256] + b1[t + 256];

    float* Er = E + r * 1792;
    Er[t]        = (v1  - mA) * rsA * ga[t]        + ba[t];
    Er[256 + t]  = (v2a - mA) * rsA * ga[256 + t]  + ba[256 + t];
    Er[512 + t]  = (v2b - mA) * rsA * ga[512 + t]  + ba[512 + t];
    Er[768 + t]  = (w0  - mA) * rsA * ga[768 + t]  + ba[768 + t];
    Er[1024 + t] = (w1  - mA) * rsA * ga[1024 + t] + ba[1024 + t];
    Er[1280 + t] = (w2  - mA) * rsA * ga[1280 + t] + ba[1280 + t];
    Er[1536 + t] = (w3  - mA) * rsA * ga[1536 + t] + ba[1536 + t];
}

// ---------------- row LN (width 512) ----------------
__global__ void ln_row512_k(const float* __restrict__ X, const float* __restrict__ g,
                            const float* __restrict__ b, float* __restrict__ Y)
{
    const long r = blockIdx.x;
    const int t = threadIdx.x;
    const float* p = X + r * 512;
    float v0 = p[t], v1 = p[t + 256];
    float s = v0 + v1, q = v0 * v0 + v1 * v1;
    blockReduce2(s, q);
    float m  = s * (1.f / 512.f);
    float rs = rsqrtf(q * (1.f / 512.f) - m * m + 1e-6f);
    Y[r * 512 + t]       = (v0 - m) * rs * g[t]       + b[t];
    Y[r * 512 + t + 256] = (v1 - m) * rs * g[t + 256] + b[t + 256];
}

// ---------------- instance-norm stats + softmax ----------------
__global__ void zero_acc_k(double* __restrict__ acc) {
    if (threadIdx.x < 64) acc[threadIdx.x] = 0.0;
}

__global__ void in_stats_k(const float* __restrict__ S, double* __restrict__ acc) {
    const int z = blockIdx.x;      // 32 maps
    const int ch = blockIdx.y;     // 16 chunks per map
    const float4* p = (const float4*)(S + (long)z * 917504 + (long)ch * 57344);
    float s = 0.f, q = 0.f;
    for (int i = threadIdx.x; i < 14336; i += 256) {
        float4 v = p[i];
        s += v.x + v.y + v.z + v.w;
        q = fmaf(v.x, v.x, q); q = fmaf(v.y, v.y, q);
        q = fmaf(v.z, v.z, q); q = fmaf(v.w, v.w, q);
    }
    blockReduce2(s, q);
    if (threadIdx.x == 0) {
        atomicAdd(&acc[z * 2], (double)s);
        atomicAdd(&acc[z * 2 + 1], (double)q);
    }
}

__global__ void inorm_softmax_k(float* __restrict__ S, const double* __restrict__ acc) {
    const int z = blockIdx.y;   // map (b*H+h)
    const int c = blockIdx.x;   // row within map
    const int t = threadIdx.x;
    const double cnt = 917504.0;
    double mu = acc[z * 2] / cnt;
    double va = acc[z * 2 + 1] / cnt - mu * mu;
    float mean = (float)mu;
    float rstd = rsqrtf((float)va + 1e-5f);

    float* row = S + (long)z * 917504 + (long)c * 1792;
    float x[7];
    float mx = -1e30f;
    #pragma unroll
    for (int i = 0; i < 7; i++) {
        x[i] = (row[t + i * 256] - mean) * rstd;
        mx = fmaxf(mx, x[i]);
    }
    mx = blockReduceMax(mx);
    float s = 0.f;
    #pragma unroll
    for (int i = 0; i < 7; i++) { x[i] = expf(x[i] - mx); s += x[i]; }
    s = blockReduceSum(s);
    float inv = 1.f / s;
    #pragma unroll
    for (int i = 0; i < 7; i++) row[t + i * 256] = x[i] * inv;
}

// ---------------- 4-way head reduce: G[b] = sum_h G4[b*4+h] ----------------
__global__ void reduce_g_k(const float4* __restrict__ G4, float4* __restrict__ G) {
    const long j = (long)blockIdx.x * 256 + threadIdx.x;   // 8 * 229376 total
    const long S4 = 917504 / 4;                            // 229376 float4 per map
    const long b = j / S4, off = j - b * S4;
    const float4* p = G4 + b * 4 * S4 + off;
    float4 r = p[0];
    float4 a1 = p[S4], a2 = p[2 * S4], a3 = p[3 * S4];
    r.x += a1.x + a2.x + a3.x;
    r.y += a1.y + a2.y + a3.y;
    r.z += a1.z + a2.z + a3.z;
    r.w += a1.w + a2.w + a3.w;
    G[j] = r;
}

// ---------------- split-K pair reduce: M[b] = P[2b] + P[2b+1] ----------------
__global__ void reduce_m_k(const float4* __restrict__ P, float4* __restrict__ M) {
    const long j = (long)blockIdx.x * 256 + threadIdx.x;   // 8 * 229376 total
    const long S4 = 917504 / 4;                            // 229376 float4 per map
    const long b = j / S4, off = j - b * S4;
    const float4* p = P + b * 2 * S4 + off;
    float4 r = p[0];
    float4 a1 = p[S4];
    r.x += a1.x; r.y += a1.y; r.z += a1.z; r.w += a1.w;
    M[j] = r;
}

// ---------------- launcher ----------------
extern "C" void kernel_launch(void* const* d_in, const int* in_sizes, int n_in,
                              void* d_out, int out_size)
{
    const float* emb1    = (const float*)d_in[0];
    const float* emb2    = (const float*)d_in[1];
    const float* emb3    = (const float*)d_in[2];
    const float* Wq      = (const float*)d_in[3];
    const float* Wk      = (const float*)d_in[4];
    const float* Wv      = (const float*)d_in[5];
    const float* Wout    = (const float*)d_in[6];
    const float* ln1_g   = (const float*)d_in[7];
    const float* ln1_b   = (const float*)d_in[8];
    const float* lnall_g = (const float*)d_in[9];
    const float* lnall_b = (const float*)d_in[10];
    const float* lnffn_g = (const float*)d_in[11];
    const float* lnffn_b = (const float*)d_in[12];
    const float* fc1_w   = (const float*)d_in[13];
    const float* fc1_b   = (const float*)d_in[14];
    const float* fc2_w   = (const float*)d_in[15];
    const float* fc2_b   = (const float*)d_in[16];

    float *X2, *E, *Mb, *T1, *S, *G, *CTX, *CX2, *XF, *H1;
    double* ACC;
    cudaGetSymbolAddress((void**)&X2,  g_X2);
    cudaGetSymbolAddress((void**)&E,   g_E);
    cudaGetSymbolAddress((void**)&Mb,  g_M);
    cudaGetSymbolAddress((void**)&T1,  g_T1);
    cudaGetSymbolAddress((void**)&S,   g_S);
    cudaGetSymbolAddress((void**)&G,   g_G);
    cudaGetSymbolAddress((void**)&CTX, g_ctx);
    cudaGetSymbolAddress((void**)&CX2, g_cx2);
    cudaGetSymbolAddress((void**)&XF,  g_Xf);
    cudaGetSymbolAddress((void**)&H1,  g_H1);
    cudaGetSymbolAddress((void**)&ACC, g_acc);

    const long SZmap = 512L * 1792L;          // 917504
    const float inv_sqrt_kv = 1.0f / sqrtf(1792.0f);

    // 1) LNs
    ln_fused_k<<<8192, 256>>>(emb1, emb2, emb3, ln1_g, ln1_b, lnall_g, lnall_b, X2, E);

    // 2) split-K=2: Mpart[b,k2] = X2[b, k2*512:(k2+1)*512]^T E[b, same rows]
    //    z = b*2 + k2, 896 CTAs (3.03 waves). Partials land in g_S (dead here).
    gemm_k<1, 0, 0><<<dim3(14, 4, 16), 256>>>(X2, E, S,
        512, 512, 1792, 1792, 1.0f,
        2, 1024L * 512, 512L * 512, 2, 1024L * 1792, 512L * 1792, SZmap,
        1, 0, 0, nullptr, nullptr);

    // 2b) M[b] = Mpart[b,0] + Mpart[b,1]
    reduce_m_k<<<7168, 256>>>((const float4*)S, (float4*)Mb);

    // 3) T1[b,h] = Wq[h]^T M[b]   (TN, K=512) grid z = b*H+h
    gemm_k<1, 0, 0><<<dim3(14, 4, 32), 256>>>(Wq, Mb, T1,
        512, 512, 1792, 1792, 1.0f,
        4, 0, 512L * 512, 4, SZmap, 0, SZmap,
        1, 0, 0, nullptr, nullptr);

    // 4) S[b,h] = T1[b,h] Wk[h] / sqrt(KV)   (NN, K=1792)
    gemm_k<0, 0, 0><<<dim3(14, 4, 32), 256>>>(T1, Wk, S,
        1792, 1792, 1792, 1792, inv_sqrt_kv,
        1, SZmap, 0, 4, 0, 1792L * 1792, SZmap,
        1, 0, 0, nullptr, nullptr);

    // 5) instance-norm stats + softmax (in place on S)
    zero_acc_k<<<1, 64>>>(ACC);
    in_stats_k<<<dim3(32, 16), 256>>>(S, ACC);
    inorm_softmax_k<<<dim3(512, 32), 256>>>(S, ACC);

    // 6) G4[b,h] = Wv[h] @ S[b,h]^T   (NT, K=1792) z = b*4+h, 1792 CTAs (6 waves)
    //    T1 is dead after step 4 -> reuse as G4 scratch.
    gemm_k<0, 1, 0><<<dim3(4, 14, 32), 256>>>(Wv, S, T1,
        1792, 1792, 1792, 512, 1.0f,
        4, 0, 1792L * 1792, 1, SZmap, 0, SZmap,
        1, 0, 0, nullptr, nullptr);

    // 6b) G[b] = sum_h G4[b,h]
    reduce_g_k<<<7168, 256>>>((const float4*)T1, (float4*)G);

    // 7) ctx[b] = E[b] G[b] / H   (NN, K=1792) grid(4, 8, 8)
    gemm_k<0, 0, 0><<<dim3(4, 8, 8), 256>>>(E, G, CTX,
        1792, 1792, 512, 512, 0.25f,
        1, 1024L * 1792, 0, 1, 1792L * 512, 0, 1024L * 512,
        1, 0, 0, nullptr, nullptr);

    // 8) cx2 = ctx Wout + emb2   (NN, K=512, EPI=add)
    gemm_k<0, 0, 1><<<dim3(4, 64, 1), 256>>>(CTX, Wout, CX2,
        512, 512, 512, 512, 1.0f,
        1, 0, 0, 1, 0, 0, 0,
        1, 0, 0, nullptr, emb2);

    // 9) Xf = LN(cx2)
    ln_row512_k<<<8192, 256>>>(CX2, lnffn_g, lnffn_b, XF);

    // 10) H1 = gelu(Xf fc1 + b1)   (NN, K=512, EPI=bias+gelu)
    gemm_k<0, 0, 2><<<dim3(16, 64, 1), 256>>>(XF, fc1_w, H1,
        512, 512, 2048, 2048, 1.0f,
        1, 0, 0, 1, 0, 0, 0,
        1, 0, 0, fc1_b, nullptr);

    // 11) out = H1 fc2 + b2 + cx2   (NN, K=2048, EPI=bias+add)
    gemm_k<0, 0, 3><<<dim3(4, 64, 1), 256>>>(H1, fc2_w, (float*)d_out,
        2048, 2048, 512, 512, 1.0f,
        1, 0, 0, 1, 0, 0, 0,
        1, 0, 0, fc2_b, CX2);
}